// round 14
// baseline (speedup 1.0000x reference)
#include <cuda_runtime.h>
#include <math.h>

// Fixed shapes: nbatch=8, numatom=512, neigh=64 -> 262144 pairs, 4096 atoms,
// natomtype=4, nwave=16, NIPSIN=3, CUTOFF=5.
#define NPAIR_SHIFT 15
#define NPAIR       (1 << NPAIR_SHIFT)
#define TOTPAIR     262144
#define TOTATOM     4096
#define NUMATOM     512
#define NWAVE       16
#define NTYPE       4
#define INV_CUTOFF  0.2f
#define CUTOFF2     25.0f
#define PI_F        3.14159265358979f
#define LOG2E_F     1.4426950408889634f
#define CAP         64     // survivors/atom: mean 17.3, sigma 4.2 -> 11 sigma
#define NBATCH      8
#define BLK_PER_B   64     // blocks per batch (512 blocks total)

// ---- device scratch (static; counters self-reset inside the kernel) ----
__device__ int    g_cnt[TOTATOM];
__device__ float4 g_geo[TOTATOM * CAP];   // {d/CUT, ux, uy, uz} finished records
__device__ float  g_cfv[TOTATOM * CAP];   // cij*fcut, spn<<4 in low mantissa bits
__device__ int    g_arrive[NBATCH];       // per-batch barrier (self-resetting)
__device__ int    g_flag[NBATCH];
__device__ int    g_done[NBATCH];

typedef unsigned long long u64;

__device__ __forceinline__ float ex2f(float x) {
    float r; asm("ex2.approx.ftz.f32 %0, %1;" : "=f"(r) : "f"(x)); return r;
}
__device__ __forceinline__ u64 pk2(float a, float b) {
    u64 r; asm("mov.b64 %0, {%1, %2};" : "=l"(r) : "f"(a), "f"(b)); return r;
}
__device__ __forceinline__ void upk2(u64 v, float& a, float& b) {
    asm("mov.b64 {%0, %1}, %2;" : "=f"(a), "=f"(b) : "l"(v));
}
__device__ __forceinline__ u64 add2(u64 a, u64 b) {
    u64 r; asm("add.rn.f32x2 %0, %1, %2;" : "=l"(r) : "l"(a), "l"(b)); return r;
}
__device__ __forceinline__ u64 mul2(u64 a, u64 b) {
    u64 r; asm("mul.rn.f32x2 %0, %1, %2;" : "=l"(r) : "l"(a), "l"(b)); return r;
}
__device__ __forceinline__ u64 fma2(u64 a, u64 b, u64 c) {
    u64 r; asm("fma.rn.f32x2 %0, %1, %2, %3;" : "=l"(r) : "l"(a), "l"(b), "l"(c)); return r;
}

// ---------------------------------------------------------------------------
// Fused kernel: phase 1 = R12 build (512 pairs/block, smem coord table),
// per-batch spin barrier, phase 2 = R13 accum (8 atoms/block, warp-per-atom).
__global__ void __launch_bounds__(256) k_fused(const float* __restrict__ coord,
                                               const int*   __restrict__ atom_index,
                                               const float* __restrict__ shifts,
                                               const int*   __restrict__ species,
                                               const float* __restrict__ params,
                                               const float* __restrict__ rs,
                                               const float* __restrict__ inta,
                                               float*       __restrict__ out) {
    __shared__ float4 s_c4[NUMATOM];           // {x,y,z, params[sp] w/ sp in low bits}
    __shared__ float2 s_rq[8][NTYPE * NWAVE];  // per-warp: {-rs/CUT, -inta*log2e}
    __shared__ float  s_dp[8][CAP];
    __shared__ float  s_ux[8][CAP];
    __shared__ float  s_uy[8][CAP];
    __shared__ float  s_uz[8][CAP];
    __shared__ float  s_cf[8][CAP];

    int tid   = threadIdx.x;
    int lane  = tid & 31;
    int wid   = tid >> 5;
    int blk   = blockIdx.x;            // 512 blocks, 64 per batch
    int b     = blk >> 6;
    int boff  = b << 9;
    int pbase = blk << 9;              // 512 pairs per block
    int lp0   = pbase & (NPAIR - 1);

    // ======== PHASE 1: build (R12 body) ========
    #pragma unroll
    for (int a = tid; a < NUMATOM; a += 256) {
        int ga = boff + a;
        float x = coord[ga * 3 + 0];
        float y = coord[ga * 3 + 1];
        float z = coord[ga * 3 + 2];
        int  sp = species[ga];
        unsigned pw = (__float_as_uint(params[sp]) & ~3u) | (unsigned)sp;
        s_c4[a] = make_float4(x, y, z, __uint_as_float(pw));
    }
    __syncthreads();

    {
        int p0 = tid * 2;              // 0..510 within block
        int2 i0v = *(const int2*)&atom_index[(b << 16) + lp0 + p0];
        int2 i1v = *(const int2*)&atom_index[(b << 16) + NPAIR + lp0 + p0];
        float2 sA = *(const float2*)&shifts[(pbase + p0) * 3 + 0];
        float2 sB = *(const float2*)&shifts[(pbase + p0) * 3 + 2];
        float2 sC = *(const float2*)&shifts[(pbase + p0) * 3 + 4];

        float sx[2] = {sA.x, sB.y};
        float sy[2] = {sA.y, sC.x};
        float sz[2] = {sB.x, sC.y};
        int   i0a[2] = {i0v.x, i0v.y};
        int   i1a[2] = {i1v.x, i1v.y};

        #pragma unroll
        for (int j = 0; j < 2; j++) {
            float4 c0 = s_c4[i0a[j]];
            float4 c1 = s_c4[i1a[j]];
            float dx = c0.x - c1.x + sx[j];
            float dy = c0.y - c1.y + sy[j];
            float dz = c0.z - c1.z + sz[j];
            float d2 = dx * dx + dy * dy + dz * dz;

            // invalid shifts (-1e9) -> huge d2 -> rejected, identical to
            // cij*valid = 0 in the reference.
            if (d2 < CUTOFF2) {
                float rinv = rsqrtf(fmaxf(d2, 1e-30f));
                float dp   = d2 * rinv * INV_CUTOFF;
                float fc   = 0.5f * (__cosf(dp * PI_F) + 1.0f);

                unsigned pw0 = __float_as_uint(c0.w), pw1 = __float_as_uint(c1.w);
                float par0 = __uint_as_float(pw0 & ~3u);
                float par1 = __uint_as_float(pw1 & ~3u);
                float cf = par0 * par1 * fc;
                unsigned cb = (__float_as_uint(cf) & ~0x3Fu) | ((pw1 & 3u) << 4);

                int i0 = boff + i0a[j];
                int pos = atomicAdd(&g_cnt[i0], 1);
                if (pos < CAP) {
                    g_geo[i0 * CAP + pos] =
                        make_float4(dp, dx * rinv, dy * rinv, dz * rinv);
                    g_cfv[i0 * CAP + pos] = __uint_as_float(cb);
                }
            }
        }
    }

    // rq tables staged BEFORE the barrier (overlaps the wait)
    #pragma unroll
    for (int i = lane; i < NTYPE * NWAVE; i += 32)
        s_rq[wid][i] = make_float2(-rs[i] * INV_CUTOFF, -inta[i] * LOG2E_F);

    // ======== per-batch barrier (deadlock-free: in-order block scheduling,
    // each batch's 64 blocks always fit on the chip, earlier batches retire) ==
    __threadfence();
    __syncthreads();
    if (tid == 0) {
        int t = atomicAdd(&g_arrive[b], 1);
        if (t == BLK_PER_B - 1) atomicExch(&g_flag[b], 1);
        while (atomicAdd(&g_flag[b], 0) == 0) __nanosleep(64);
    }
    __syncthreads();
    __threadfence();

    // ======== PHASE 2: accum (R13 body), atom = this block's slice ========
    int atom = boff + ((blk & 63) << 3) + wid;

    int cnt = min(g_cnt[atom], CAP);
    if (lane == 0) g_cnt[atom] = 0;            // self-reset for next replay
    int cntp = (cnt + 3) & ~3;

    for (int i = lane; i < cntp; i += 32) {
        if (i < cnt) {
            float4 g = __ldg(&g_geo[atom * CAP + i]);
            float  c = __ldg(&g_cfv[atom * CAP + i]);
            s_dp[wid][i] = g.x;
            s_ux[wid][i] = g.y;
            s_uy[wid][i] = g.z;
            s_uz[wid][i] = g.w;
            s_cf[wid][i] = c;
        } else {
            s_dp[wid][i] = 0.f; s_ux[wid][i] = 0.f; s_uy[wid][i] = 0.f;
            s_uz[wid][i] = 0.f; s_cf[wid][i] = 0.f;
        }
    }
    __syncwarp();

    int k    = lane & 15;
    int half = lane >> 4;
    const float2* rqw = s_rq[wid];

    u64 a0_2 = 0, ax2 = 0, ay2 = 0, az2 = 0;
    u64 axx2 = 0, ayy2 = 0, azz2 = 0, axy2 = 0, axz2 = 0, ayz2 = 0;

    for (int pp = half * 2; pp < cntp; pp += 4) {
        u64 dp2 = *(const u64*)&s_dp[wid][pp];
        u64 ux2 = *(const u64*)&s_ux[wid][pp];
        u64 uy2 = *(const u64*)&s_uy[wid][pp];
        u64 uz2 = *(const u64*)&s_uz[wid][pp];
        u64 cf2 = *(const u64*)&s_cf[wid][pp];

        float cfA, cfB; upk2(cf2, cfA, cfB);
        float2 rqA = rqw[(__float_as_uint(cfA) & 0x30u) + k];
        float2 rqB = rqw[(__float_as_uint(cfB) & 0x30u) + k];

        u64 t2 = add2(dp2, pk2(rqA.x, rqB.x));
        u64 m2 = mul2(pk2(rqA.y, rqB.y), mul2(t2, t2));
        float mA, mB; upk2(m2, mA, mB);
        u64 w2 = mul2(pk2(ex2f(mA), ex2f(mB)), cf2);

        u64 wx2 = mul2(w2, ux2);
        u64 wy2 = mul2(w2, uy2);
        u64 wz2 = mul2(w2, uz2);

        a0_2 = add2(a0_2, w2);
        ax2  = add2(ax2, wx2);
        ay2  = add2(ay2, wy2);
        az2  = add2(az2, wz2);
        axx2 = fma2(wx2, ux2, axx2);
        ayy2 = fma2(wy2, uy2, ayy2);
        azz2 = fma2(wz2, uz2, azz2);
        axy2 = fma2(wx2, uy2, axy2);
        axz2 = fma2(wx2, uz2, axz2);
        ayz2 = fma2(wy2, uz2, ayz2);
    }

    float lo, hi;
    upk2(a0_2, lo, hi);  float a0  = lo + hi;
    upk2(ax2,  lo, hi);  float ax  = lo + hi;
    upk2(ay2,  lo, hi);  float ay  = lo + hi;
    upk2(az2,  lo, hi);  float az  = lo + hi;
    upk2(axx2, lo, hi);  float axx = lo + hi;
    upk2(ayy2, lo, hi);  float ayy = lo + hi;
    upk2(azz2, lo, hi);  float azz = lo + hi;
    upk2(axy2, lo, hi);  float axy = lo + hi;
    upk2(axz2, lo, hi);  float axz = lo + hi;
    upk2(ayz2, lo, hi);  float ayz = lo + hi;

    a0  += __shfl_xor_sync(0xffffffffu, a0,  16);
    ax  += __shfl_xor_sync(0xffffffffu, ax,  16);
    ay  += __shfl_xor_sync(0xffffffffu, ay,  16);
    az  += __shfl_xor_sync(0xffffffffu, az,  16);
    axx += __shfl_xor_sync(0xffffffffu, axx, 16);
    ayy += __shfl_xor_sync(0xffffffffu, ayy, 16);
    azz += __shfl_xor_sync(0xffffffffu, azz, 16);
    axy += __shfl_xor_sync(0xffffffffu, axy, 16);
    axz += __shfl_xor_sync(0xffffffffu, axz, 16);
    ayz += __shfl_xor_sync(0xffffffffu, ayz, 16);

    if (half == 0) {
        float o0 = a0 * a0;
        float o1 = ax * ax + ay * ay + az * az;
        float o2v = axx * axx + ayy * ayy + azz * azz
                  + 2.0f * (axy * axy + axz * axz + ayz * ayz);
        float* o = out + atom * (3 * NWAVE);
        o[k]             = o0;
        o[NWAVE + k]     = o1;
        o[2 * NWAVE + k] = o2v;
    }

    // ---- barrier self-reset: last finished block of the batch cleans up ----
    __syncthreads();
    if (tid == 0) {
        int t = atomicAdd(&g_done[b], 1);
        if (t == BLK_PER_B - 1) {
            g_arrive[b] = 0;
            g_flag[b]   = 0;
            g_done[b]   = 0;
        }
    }
}

// ---------------------------------------------------------------------------
extern "C" void kernel_launch(void* const* d_in, const int* in_sizes, int n_in,
                              void* d_out, int out_size) {
    const float* coordinates = (const float*)d_in[0];
    const int*   atom_index  = (const int*)  d_in[2];
    const float* shifts      = (const float*)d_in[3];
    const int*   species     = (const int*)  d_in[4];
    const float* rs          = (const float*)d_in[5];
    const float* inta        = (const float*)d_in[6];
    const float* params      = (const float*)d_in[7];
    float* out = (float*)d_out;

    k_fused<<<TOTPAIR / 512, 256>>>(coordinates, atom_index, shifts, species,
                                    params, rs, inta, out);
}

// round 15
// speedup vs baseline: 1.1369x; 1.1369x over previous
#include <cuda_runtime.h>
#include <math.h>

// Fixed shapes: nbatch=8, numatom=512, neigh=64 -> 262144 pairs, 4096 atoms,
// natomtype=4, nwave=16, NIPSIN=3, CUTOFF=5.
#define NPAIR_SHIFT 15
#define NPAIR       (1 << NPAIR_SHIFT)
#define TOTPAIR     262144
#define TOTATOM     4096
#define NUMATOM     512
#define NWAVE       16
#define NTYPE       4
#define INV_CUTOFF  0.2f
#define CUTOFF2     25.0f
#define PI_F        3.14159265358979f
#define LOG2E_F     1.4426950408889634f
#define CAP         64     // survivors/atom: mean 17.3, sigma 4.2 -> 11 sigma
#define NBATCH      8
#define BLK_PER_B   64     // blocks per batch (512 blocks total)

// ---- device scratch (static; counters/barrier self-reset inside kernel) ----
__device__ int    g_cnt[TOTATOM];
__device__ float4 g_geo[TOTATOM * CAP];   // {d/CUT, ux, uy, uz} finished records
__device__ float  g_cfv[TOTATOM * CAP];   // cij*fcut, spn<<4 in low mantissa bits
__device__ int    g_arrive[NBATCH];
__device__ int    g_flag[NBATCH];
__device__ int    g_done[NBATCH];

typedef unsigned long long u64;

__device__ __forceinline__ float ex2f(float x) {
    float r; asm("ex2.approx.ftz.f32 %0, %1;" : "=f"(r) : "f"(x)); return r;
}
__device__ __forceinline__ u64 pk2(float a, float b) {
    u64 r; asm("mov.b64 %0, {%1, %2};" : "=l"(r) : "f"(a), "f"(b)); return r;
}
__device__ __forceinline__ void upk2(u64 v, float& a, float& b) {
    asm("mov.b64 {%0, %1}, %2;" : "=f"(a), "=f"(b) : "l"(v));
}
__device__ __forceinline__ u64 add2(u64 a, u64 b) {
    u64 r; asm("add.rn.f32x2 %0, %1, %2;" : "=l"(r) : "l"(a), "l"(b)); return r;
}
__device__ __forceinline__ u64 mul2(u64 a, u64 b) {
    u64 r; asm("mul.rn.f32x2 %0, %1, %2;" : "=l"(r) : "l"(a), "l"(b)); return r;
}
__device__ __forceinline__ u64 fma2(u64 a, u64 b, u64 c) {
    u64 r; asm("fma.rn.f32x2 %0, %1, %2, %3;" : "=l"(r) : "l"(a), "l"(b), "l"(c)); return r;
}

// Overlay sizes: phase 1 uses s_c4 (512 x float4 = 8192 B); phase 2 uses the
// five SoA arrays (5 x 8 x 64 x 4 = 10240 B). They never coexist.
#define OVL_BYTES  10240

// ---------------------------------------------------------------------------
// Fused kernel, residency-guaranteed: smem ~14.5 KB (overlay) and
// __launch_bounds__(256,4) -> 4 blocks/SM -> 592 slots >= 512 blocks, so the
// whole grid is co-resident and the per-batch barrier costs only skew.
__global__ void __launch_bounds__(256, 4) k_fused(const float* __restrict__ coord,
                                                  const int*   __restrict__ atom_index,
                                                  const float* __restrict__ shifts,
                                                  const int*   __restrict__ species,
                                                  const float* __restrict__ params,
                                                  const float* __restrict__ rs,
                                                  const float* __restrict__ inta,
                                                  float*       __restrict__ out) {
    __shared__ __align__(16) unsigned char s_ovl[OVL_BYTES];
    __shared__ float2 s_rq[8][NTYPE * NWAVE];  // per-warp: {-rs/CUT, -inta*log2e}

    float4* s_c4 = reinterpret_cast<float4*>(s_ovl);                   // phase 1
    float (*s_dp)[CAP] = reinterpret_cast<float(*)[CAP]>(s_ovl);       // phase 2
    float (*s_ux)[CAP] = reinterpret_cast<float(*)[CAP]>(s_ovl + 2048);
    float (*s_uy)[CAP] = reinterpret_cast<float(*)[CAP]>(s_ovl + 4096);
    float (*s_uz)[CAP] = reinterpret_cast<float(*)[CAP]>(s_ovl + 6144);
    float (*s_cf)[CAP] = reinterpret_cast<float(*)[CAP]>(s_ovl + 8192);

    int tid   = threadIdx.x;
    int lane  = tid & 31;
    int wid   = tid >> 5;
    int blk   = blockIdx.x;            // 512 blocks, 64 per batch
    int b     = blk >> 6;
    int boff  = b << 9;
    int pbase = blk << 9;              // 512 pairs per block
    int lp0   = pbase & (NPAIR - 1);

    // ======== PHASE 1: build (R12/R13 body) ========
    #pragma unroll
    for (int a = tid; a < NUMATOM; a += 256) {
        int ga = boff + a;
        float x = coord[ga * 3 + 0];
        float y = coord[ga * 3 + 1];
        float z = coord[ga * 3 + 2];
        int  sp = species[ga];
        unsigned pw = (__float_as_uint(params[sp]) & ~3u) | (unsigned)sp;
        s_c4[a] = make_float4(x, y, z, __uint_as_float(pw));
    }
    __syncthreads();

    {
        int p0 = tid * 2;              // 0..510 within block
        int2 i0v = *(const int2*)&atom_index[(b << 16) + lp0 + p0];
        int2 i1v = *(const int2*)&atom_index[(b << 16) + NPAIR + lp0 + p0];
        float2 sA = *(const float2*)&shifts[(pbase + p0) * 3 + 0];
        float2 sB = *(const float2*)&shifts[(pbase + p0) * 3 + 2];
        float2 sC = *(const float2*)&shifts[(pbase + p0) * 3 + 4];

        float sx[2] = {sA.x, sB.y};
        float sy[2] = {sA.y, sC.x};
        float sz[2] = {sB.x, sC.y};
        int   i0a[2] = {i0v.x, i0v.y};
        int   i1a[2] = {i1v.x, i1v.y};

        #pragma unroll
        for (int j = 0; j < 2; j++) {
            float4 c0 = s_c4[i0a[j]];
            float4 c1 = s_c4[i1a[j]];
            float dx = c0.x - c1.x + sx[j];
            float dy = c0.y - c1.y + sy[j];
            float dz = c0.z - c1.z + sz[j];
            float d2 = dx * dx + dy * dy + dz * dz;

            // invalid shifts (-1e9) -> huge d2 -> rejected (== cij*valid = 0)
            if (d2 < CUTOFF2) {
                float rinv = rsqrtf(fmaxf(d2, 1e-30f));
                float dp   = d2 * rinv * INV_CUTOFF;
                float fc   = 0.5f * (__cosf(dp * PI_F) + 1.0f);

                unsigned pw0 = __float_as_uint(c0.w), pw1 = __float_as_uint(c1.w);
                float par0 = __uint_as_float(pw0 & ~3u);
                float par1 = __uint_as_float(pw1 & ~3u);
                float cf = par0 * par1 * fc;
                unsigned cb = (__float_as_uint(cf) & ~0x3Fu) | ((pw1 & 3u) << 4);

                int i0 = boff + i0a[j];
                int pos = atomicAdd(&g_cnt[i0], 1);
                if (pos < CAP) {
                    g_geo[i0 * CAP + pos] =
                        make_float4(dp, dx * rinv, dy * rinv, dz * rinv);
                    g_cfv[i0 * CAP + pos] = __uint_as_float(cb);
                }
            }
        }
    }

    // rq tables staged BEFORE the barrier (overlaps the wait; not in overlay)
    #pragma unroll
    for (int i = lane; i < NTYPE * NWAVE; i += 32)
        s_rq[wid][i] = make_float2(-rs[i] * INV_CUTOFF, -inta[i] * LOG2E_F);

    // ======== per-batch barrier (entire grid co-resident => skew only) ======
    __threadfence();
    __syncthreads();                    // also retires all s_c4 reads (overlay!)
    if (tid == 0) {
        int t = atomicAdd(&g_arrive[b], 1);
        if (t == BLK_PER_B - 1) atomicExch(&g_flag[b], 1);
        while (atomicAdd(&g_flag[b], 0) == 0) __nanosleep(64);
    }
    __syncthreads();
    __threadfence();

    // ======== PHASE 2: accum (R13 body), one warp per atom ========
    int atom = boff + ((blk & 63) << 3) + wid;

    int cnt = min(g_cnt[atom], CAP);
    if (lane == 0) g_cnt[atom] = 0;            // self-reset for next replay
    int cntp = (cnt + 3) & ~3;

    for (int i = lane; i < cntp; i += 32) {
        if (i < cnt) {
            float4 g = __ldg(&g_geo[atom * CAP + i]);
            float  c = __ldg(&g_cfv[atom * CAP + i]);
            s_dp[wid][i] = g.x;
            s_ux[wid][i] = g.y;
            s_uy[wid][i] = g.z;
            s_uz[wid][i] = g.w;
            s_cf[wid][i] = c;
        } else {
            s_dp[wid][i] = 0.f; s_ux[wid][i] = 0.f; s_uy[wid][i] = 0.f;
            s_uz[wid][i] = 0.f; s_cf[wid][i] = 0.f;
        }
    }
    __syncwarp();

    int k    = lane & 15;
    int half = lane >> 4;
    const float2* rqw = s_rq[wid];

    u64 a0_2 = 0, ax2 = 0, ay2 = 0, az2 = 0;
    u64 axx2 = 0, ayy2 = 0, azz2 = 0, axy2 = 0, axz2 = 0, ayz2 = 0;

    for (int pp = half * 2; pp < cntp; pp += 4) {
        u64 dp2 = *(const u64*)&s_dp[wid][pp];
        u64 ux2 = *(const u64*)&s_ux[wid][pp];
        u64 uy2 = *(const u64*)&s_uy[wid][pp];
        u64 uz2 = *(const u64*)&s_uz[wid][pp];
        u64 cf2 = *(const u64*)&s_cf[wid][pp];

        float cfA, cfB; upk2(cf2, cfA, cfB);
        float2 rqA = rqw[(__float_as_uint(cfA) & 0x30u) + k];
        float2 rqB = rqw[(__float_as_uint(cfB) & 0x30u) + k];

        u64 t2 = add2(dp2, pk2(rqA.x, rqB.x));
        u64 m2 = mul2(pk2(rqA.y, rqB.y), mul2(t2, t2));
        float mA, mB; upk2(m2, mA, mB);
        u64 w2 = mul2(pk2(ex2f(mA), ex2f(mB)), cf2);

        u64 wx2 = mul2(w2, ux2);
        u64 wy2 = mul2(w2, uy2);
        u64 wz2 = mul2(w2, uz2);

        a0_2 = add2(a0_2, w2);
        ax2  = add2(ax2, wx2);
        ay2  = add2(ay2, wy2);
        az2  = add2(az2, wz2);
        axx2 = fma2(wx2, ux2, axx2);
        ayy2 = fma2(wy2, uy2, ayy2);
        azz2 = fma2(wz2, uz2, azz2);
        axy2 = fma2(wx2, uy2, axy2);
        axz2 = fma2(wx2, uz2, axz2);
        ayz2 = fma2(wy2, uz2, ayz2);
    }

    float lo, hi;
    upk2(a0_2, lo, hi);  float a0  = lo + hi;
    upk2(ax2,  lo, hi);  float ax  = lo + hi;
    upk2(ay2,  lo, hi);  float ay  = lo + hi;
    upk2(az2,  lo, hi);  float az  = lo + hi;
    upk2(axx2, lo, hi);  float axx = lo + hi;
    upk2(ayy2, lo, hi);  float ayy = lo + hi;
    upk2(azz2, lo, hi);  float azz = lo + hi;
    upk2(axy2, lo, hi);  float axy = lo + hi;
    upk2(axz2, lo, hi);  float axz = lo + hi;
    upk2(ayz2, lo, hi);  float ayz = lo + hi;

    a0  += __shfl_xor_sync(0xffffffffu, a0,  16);
    ax  += __shfl_xor_sync(0xffffffffu, ax,  16);
    ay  += __shfl_xor_sync(0xffffffffu, ay,  16);
    az  += __shfl_xor_sync(0xffffffffu, az,  16);
    axx += __shfl_xor_sync(0xffffffffu, axx, 16);
    ayy += __shfl_xor_sync(0xffffffffu, ayy, 16);
    azz += __shfl_xor_sync(0xffffffffu, azz, 16);
    axy += __shfl_xor_sync(0xffffffffu, axy, 16);
    axz += __shfl_xor_sync(0xffffffffu, axz, 16);
    ayz += __shfl_xor_sync(0xffffffffu, ayz, 16);

    if (half == 0) {
        float o0 = a0 * a0;
        float o1 = ax * ax + ay * ay + az * az;
        float o2v = axx * axx + ayy * ayy + azz * azz
                  + 2.0f * (axy * axy + axz * axz + ayz * ayz);
        float* o = out + atom * (3 * NWAVE);
        o[k]             = o0;
        o[NWAVE + k]     = o1;
        o[2 * NWAVE + k] = o2v;
    }

    // ---- barrier self-reset: last finished block of the batch cleans up ----
    __syncthreads();
    if (tid == 0) {
        int t = atomicAdd(&g_done[b], 1);
        if (t == BLK_PER_B - 1) {
            g_arrive[b] = 0;
            g_flag[b]   = 0;
            g_done[b]   = 0;
        }
    }
}

// ---------------------------------------------------------------------------
extern "C" void kernel_launch(void* const* d_in, const int* in_sizes, int n_in,
                              void* d_out, int out_size) {
    const float* coordinates = (const float*)d_in[0];
    const int*   atom_index  = (const int*)  d_in[2];
    const float* shifts      = (const float*)d_in[3];
    const int*   species     = (const int*)  d_in[4];
    const float* rs          = (const float*)d_in[5];
    const float* inta        = (const float*)d_in[6];
    const float* params      = (const float*)d_in[7];
    float* out = (float*)d_out;

    k_fused<<<TOTPAIR / 512, 256>>>(coordinates, atom_index, shifts, species,
                                    params, rs, inta, out);
}

// round 16
// speedup vs baseline: 1.6566x; 1.4571x over previous
#include <cuda_runtime.h>
#include <math.h>

// Fixed shapes: nbatch=8, numatom=512, neigh=64 -> 262144 pairs, 4096 atoms,
// natomtype=4, nwave=16, NIPSIN=3, CUTOFF=5.
#define NPAIR_SHIFT 15
#define NPAIR       (1 << NPAIR_SHIFT)
#define TOTPAIR     262144
#define TOTATOM     4096
#define NUMATOM     512
#define NWAVE       16
#define NTYPE       4
#define INV_CUTOFF  0.2f
#define CUTOFF2     25.0f
#define PI_F        3.14159265358979f
#define LOG2E_F     1.4426950408889634f
#define CAP         64     // survivors/atom: mean 17.3, sigma 4.2 -> 11 sigma

// ---- device scratch (static; counters self-reset inside k_accum) ----
__device__ int    g_cnt[TOTATOM];
__device__ float4 g_geo[TOTATOM * CAP];   // {d/CUT, ux, uy, uz} finished records
__device__ float  g_cfv[TOTATOM * CAP];   // cij*fcut, spn<<4 in low mantissa bits

typedef unsigned long long u64;

__device__ __forceinline__ float ex2f(float x) {
    float r; asm("ex2.approx.ftz.f32 %0, %1;" : "=f"(r) : "f"(x)); return r;
}
__device__ __forceinline__ u64 pk2(float a, float b) {
    u64 r; asm("mov.b64 %0, {%1, %2};" : "=l"(r) : "f"(a), "f"(b)); return r;
}
__device__ __forceinline__ void upk2(u64 v, float& a, float& b) {
    asm("mov.b64 {%0, %1}, %2;" : "=f"(a), "=f"(b) : "l"(v));
}
__device__ __forceinline__ u64 add2(u64 a, u64 b) {
    u64 r; asm("add.rn.f32x2 %0, %1, %2;" : "=l"(r) : "l"(a), "l"(b)); return r;
}
__device__ __forceinline__ u64 mul2(u64 a, u64 b) {
    u64 r; asm("mul.rn.f32x2 %0, %1, %2;" : "=l"(r) : "l"(a), "l"(b)); return r;
}
__device__ __forceinline__ u64 fma2(u64 a, u64 b, u64 c) {
    u64 r; asm("fma.rn.f32x2 %0, %1, %2, %3;" : "=l"(r) : "l"(a), "l"(b), "l"(c)); return r;
}

// ---------------------------------------------------------------------------
// Pass 1 (R12/R13, measured ~4.5us): block = 512 consecutive pairs in one
// batch; batch's 512-atom packed coord/param table in smem; exact cutoff
// filter so only ~27% of pairs reach rsqrt/cos + atomic + store.
__global__ void __launch_bounds__(256) k_build(const float* __restrict__ coord,
                                               const int*   __restrict__ atom_index,
                                               const float* __restrict__ shifts,
                                               const int*   __restrict__ species,
                                               const float* __restrict__ params) {
    __shared__ float4 s_c4[NUMATOM];   // {x, y, z, params[sp] w/ sp in low 2 bits}

    int tid   = threadIdx.x;
    int blk   = blockIdx.x;            // 512 blocks, 64 per batch
    int b     = blk >> 6;
    int boff  = b << 9;
    int pbase = blk << 9;              // 512 pairs per block
    int lp0   = pbase & (NPAIR - 1);

    #pragma unroll
    for (int a = tid; a < NUMATOM; a += 256) {
        int ga = boff + a;
        float x = coord[ga * 3 + 0];
        float y = coord[ga * 3 + 1];
        float z = coord[ga * 3 + 2];
        int  sp = species[ga];
        unsigned pw = (__float_as_uint(params[sp]) & ~3u) | (unsigned)sp;
        s_c4[a] = make_float4(x, y, z, __uint_as_float(pw));
    }
    __syncthreads();

    int p0 = tid * 2;                  // 0..510 within block
    int2 i0v = *(const int2*)&atom_index[(b << 16) + lp0 + p0];
    int2 i1v = *(const int2*)&atom_index[(b << 16) + NPAIR + lp0 + p0];
    float2 sA = *(const float2*)&shifts[(pbase + p0) * 3 + 0];
    float2 sB = *(const float2*)&shifts[(pbase + p0) * 3 + 2];
    float2 sC = *(const float2*)&shifts[(pbase + p0) * 3 + 4];

    float sx[2] = {sA.x, sB.y};
    float sy[2] = {sA.y, sC.x};
    float sz[2] = {sB.x, sC.y};
    int   i0a[2] = {i0v.x, i0v.y};
    int   i1a[2] = {i1v.x, i1v.y};

    #pragma unroll
    for (int j = 0; j < 2; j++) {
        float4 c0 = s_c4[i0a[j]];      // LDS.128
        float4 c1 = s_c4[i1a[j]];
        float dx = c0.x - c1.x + sx[j];
        float dy = c0.y - c1.y + sy[j];
        float dz = c0.z - c1.z + sz[j];
        float d2 = dx * dx + dy * dy + dz * dz;

        // invalid shifts (-1e9) -> huge d2 -> rejected, identical to
        // cij*valid = 0 in the reference.
        if (d2 < CUTOFF2) {
            float rinv = rsqrtf(fmaxf(d2, 1e-30f));
            float dp   = d2 * rinv * INV_CUTOFF;
            float fc   = 0.5f * (__cosf(dp * PI_F) + 1.0f);

            unsigned pw0 = __float_as_uint(c0.w), pw1 = __float_as_uint(c1.w);
            float par0 = __uint_as_float(pw0 & ~3u);
            float par1 = __uint_as_float(pw1 & ~3u);
            float cf = par0 * par1 * fc;
            unsigned cb = (__float_as_uint(cf) & ~0x3Fu) | ((pw1 & 3u) << 4);

            int i0 = boff + i0a[j];
            int pos = atomicAdd(&g_cnt[i0], 1);
            if (pos < CAP) {
                g_geo[i0 * CAP + pos] = make_float4(dp, dx * rinv, dy * rinv, dz * rinv);
                g_cfv[i0 * CAP + pos] = __uint_as_float(cb);
            }
        }
    }
}

// ---------------------------------------------------------------------------
// Pass 2 (R13 + micro-fixes): one warp per atom, warp-autonomous.
// cnt issued first; rq table staged with vector loads (1 LDG.64 pair +
// 1 STS.128 per lane); simple cnt-gated staging; packed f32x2 loop.
__global__ void __launch_bounds__(256) k_accum(const float* __restrict__ rs,
                                               const float* __restrict__ inta,
                                               float*       __restrict__ out) {
    __shared__ float2 s_rq[8][NTYPE * NWAVE];  // per-warp: {-rs/CUT, -inta*log2e}
    __shared__ float  s_dp[8][CAP];
    __shared__ float  s_ux[8][CAP];
    __shared__ float  s_uy[8][CAP];
    __shared__ float  s_uz[8][CAP];
    __shared__ float  s_cf[8][CAP];

    int tid  = threadIdx.x;
    int lane = tid & 31;
    int wid  = tid >> 5;
    int atom = blockIdx.x * 8 + wid;

    int cnt = min(g_cnt[atom], CAP);           // issue first

    // vectorized rq staging: lane covers entries 2*lane, 2*lane+1
    {
        float2 r2 = *(const float2*)&rs[lane * 2];
        float2 q2 = *(const float2*)&inta[lane * 2];
        float4 v = make_float4(-r2.x * INV_CUTOFF, -q2.x * LOG2E_F,
                               -r2.y * INV_CUTOFF, -q2.y * LOG2E_F);
        *(float4*)&s_rq[wid][lane * 2] = v;    // STS.128
    }

    int cntp = (cnt + 3) & ~3;

    // ---- stage survivors into SoA smem (coalesced; usually 1 iteration) ----
    for (int i = lane; i < cntp; i += 32) {
        if (i < cnt) {
            float4 g = __ldg(&g_geo[atom * CAP + i]);
            float  c = __ldg(&g_cfv[atom * CAP + i]);
            s_dp[wid][i] = g.x;
            s_ux[wid][i] = g.y;
            s_uy[wid][i] = g.z;
            s_uz[wid][i] = g.w;
            s_cf[wid][i] = c;
        } else {
            s_dp[wid][i] = 0.f; s_ux[wid][i] = 0.f; s_uy[wid][i] = 0.f;
            s_uz[wid][i] = 0.f; s_cf[wid][i] = 0.f;
        }
    }
    if (lane == 0) g_cnt[atom] = 0;            // self-reset, off critical path
    __syncwarp();

    // ---- packed f32x2 channel loop: 2 streams (halves) x 2 pairs/iter ----
    int k    = lane & 15;
    int half = lane >> 4;
    const float2* rqw = s_rq[wid];

    u64 a0_2 = 0, ax2 = 0, ay2 = 0, az2 = 0;
    u64 axx2 = 0, ayy2 = 0, azz2 = 0, axy2 = 0, axz2 = 0, ayz2 = 0;

    for (int pp = half * 2; pp < cntp; pp += 4) {
        u64 dp2 = *(const u64*)&s_dp[wid][pp];
        u64 ux2 = *(const u64*)&s_ux[wid][pp];
        u64 uy2 = *(const u64*)&s_uy[wid][pp];
        u64 uz2 = *(const u64*)&s_uz[wid][pp];
        u64 cf2 = *(const u64*)&s_cf[wid][pp];

        float cfA, cfB; upk2(cf2, cfA, cfB);
        float2 rqA = rqw[(__float_as_uint(cfA) & 0x30u) + k];
        float2 rqB = rqw[(__float_as_uint(cfB) & 0x30u) + k];

        u64 t2 = add2(dp2, pk2(rqA.x, rqB.x));
        u64 m2 = mul2(pk2(rqA.y, rqB.y), mul2(t2, t2));
        float mA, mB; upk2(m2, mA, mB);
        u64 w2 = mul2(pk2(ex2f(mA), ex2f(mB)), cf2);

        u64 wx2 = mul2(w2, ux2);
        u64 wy2 = mul2(w2, uy2);
        u64 wz2 = mul2(w2, uz2);

        a0_2 = add2(a0_2, w2);
        ax2  = add2(ax2, wx2);
        ay2  = add2(ay2, wy2);
        az2  = add2(az2, wz2);
        axx2 = fma2(wx2, ux2, axx2);
        ayy2 = fma2(wy2, uy2, ayy2);
        azz2 = fma2(wz2, uz2, azz2);
        axy2 = fma2(wx2, uy2, axy2);
        axz2 = fma2(wx2, uz2, axz2);
        ayz2 = fma2(wy2, uz2, ayz2);
    }

    float lo, hi;
    upk2(a0_2, lo, hi);  float a0  = lo + hi;
    upk2(ax2,  lo, hi);  float ax  = lo + hi;
    upk2(ay2,  lo, hi);  float ay  = lo + hi;
    upk2(az2,  lo, hi);  float az  = lo + hi;
    upk2(axx2, lo, hi);  float axx = lo + hi;
    upk2(ayy2, lo, hi);  float ayy = lo + hi;
    upk2(azz2, lo, hi);  float azz = lo + hi;
    upk2(axy2, lo, hi);  float axy = lo + hi;
    upk2(axz2, lo, hi);  float axz = lo + hi;
    upk2(ayz2, lo, hi);  float ayz = lo + hi;

    a0  += __shfl_xor_sync(0xffffffffu, a0,  16);
    ax  += __shfl_xor_sync(0xffffffffu, ax,  16);
    ay  += __shfl_xor_sync(0xffffffffu, ay,  16);
    az  += __shfl_xor_sync(0xffffffffu, az,  16);
    axx += __shfl_xor_sync(0xffffffffu, axx, 16);
    ayy += __shfl_xor_sync(0xffffffffu, ayy, 16);
    azz += __shfl_xor_sync(0xffffffffu, azz, 16);
    axy += __shfl_xor_sync(0xffffffffu, axy, 16);
    axz += __shfl_xor_sync(0xffffffffu, axz, 16);
    ayz += __shfl_xor_sync(0xffffffffu, ayz, 16);

    if (half == 0) {
        float o0 = a0 * a0;
        float o1 = ax * ax + ay * ay + az * az;
        float o2v = axx * axx + ayy * ayy + azz * azz
                  + 2.0f * (axy * axy + axz * axz + ayz * ayz);
        float* o = out + atom * (3 * NWAVE);
        o[k]             = o0;
        o[NWAVE + k]     = o1;
        o[2 * NWAVE + k] = o2v;
    }
}

// ---------------------------------------------------------------------------
extern "C" void kernel_launch(void* const* d_in, const int* in_sizes, int n_in,
                              void* d_out, int out_size) {
    const float* coordinates = (const float*)d_in[0];
    const int*   atom_index  = (const int*)  d_in[2];
    const float* shifts      = (const float*)d_in[3];
    const int*   species     = (const int*)  d_in[4];
    const float* rs          = (const float*)d_in[5];
    const float* inta        = (const float*)d_in[6];
    const float* params      = (const float*)d_in[7];
    float* out = (float*)d_out;

    k_build<<<TOTPAIR / 512, 256>>>(coordinates, atom_index, shifts, species, params);
    k_accum<<<TOTATOM / 8, 256>>>(rs, inta, out);
}